// round 15
// baseline (speedup 1.0000x reference)
#include <cuda_runtime.h>
#include <cuda_bf16.h>
#include <cstdint>

// ---------------- problem constants ----------------
#define BATCH  1024
#define INSZ   512
#define UNITS  512
#define K12    12
#define KDIM   (INSZ * K12)      // 6144
#define KSPLIT 4
#define KPER   (KDIM / KSPLIT)   // 1536
#define TK     64                // K columns per stage (128 B/row bf16)
#define STAGES (KPER / TK)       // 24
#define PIPE   4                 // cp.async pipeline depth

// fused prep dispatch (256 threads each, NO smem anywhere)
#define PREP_A_BLOCKS   ((BATCH * INSZ) / 256)        // 2048
#define PREP_BT_BLOCKS  ((UNITS / 32) * (INSZ / 64))  // 128: 16 o-tiles x 8 i-tiles
#define PREP_OUT_BLOCKS ((BATCH * UNITS / 4) / 256)   // 512

// ---------------- scratch ----------------
__device__ __align__(16) __nv_bfloat16 g_A[(size_t)BATCH * KDIM];     // 12.6 MB
__device__ __align__(16) __nv_bfloat16 g_Bt[(size_t)UNITS * KDIM];    // 6.3 MB

// ---------------- helpers ----------------
__device__ __forceinline__ uint32_t smem_u32(const void* p) {
    uint32_t a;
    asm("{ .reg .u64 t; cvta.to.shared.u64 t, %1; cvt.u32.u64 %0, t; }" : "=r"(a) : "l"(p));
    return a;
}
__device__ __forceinline__ uint32_t swz(uint32_t off) { return off ^ ((off >> 3) & 0x70); }

__device__ __forceinline__ void cp_async16(uint32_t saddr, const void* g) {
    asm volatile("cp.async.cg.shared.global [%0], [%1], 16;" :: "r"(saddr), "l"(g) : "memory");
}
#define CP_COMMIT() asm volatile("cp.async.commit_group;" ::: "memory")
#define CP_WAIT(N)  asm volatile("cp.async.wait_group %0;" :: "n"(N) : "memory")

__device__ __forceinline__ void ldsm_x4(uint32_t& r0, uint32_t& r1, uint32_t& r2, uint32_t& r3,
                                        uint32_t addr) {
    asm volatile("ldmatrix.sync.aligned.m8n8.x4.shared.b16 {%0,%1,%2,%3}, [%4];"
                 : "=r"(r0), "=r"(r1), "=r"(r2), "=r"(r3) : "r"(addr));
}
__device__ __forceinline__ void mma16816(float* c, const uint32_t* a, uint32_t b0, uint32_t b1) {
    asm volatile("mma.sync.aligned.m16n8k16.row.col.f32.bf16.bf16.f32 "
                 "{%0,%1,%2,%3}, {%4,%5,%6,%7}, {%8,%9}, {%0,%1,%2,%3};"
                 : "+f"(c[0]), "+f"(c[1]), "+f"(c[2]), "+f"(c[3])
                 : "r"(a[0]), "r"(a[1]), "r"(a[2]), "r"(a[3]), "r"(b0), "r"(b1));
}
__device__ __forceinline__ void red_add_f32(float* p, float v) {
    asm volatile("red.global.add.f32 [%0], %1;" :: "l"(p), "f"(v) : "memory");
}
__device__ __forceinline__ unsigned pkb(__nv_bfloat16 a, __nv_bfloat16 b) {
    return (unsigned)__bfloat16_as_ushort(a) | ((unsigned)__bfloat16_as_ushort(b) << 16);
}

// ---------------- fused prep (NO smem): build_A | build_Bt(direct) | init_out ----------------
__global__ void prep(const float* __restrict__ X, const float* __restrict__ Wk,
                     const float* __restrict__ scale, const float* __restrict__ bias,
                     float* __restrict__ out) {
    int blk = blockIdx.x;
    if (blk < PREP_A_BLOCKS) {
        // ---- build_A: A[b, i*12 + c] = {8 cubic B-spline bases, shi, shi, slo, 0} ----
        int lin = blk * 256 + threadIdx.x;
        float x = X[lin];
        float bb[11];
#pragma unroll
        for (int j = 0; j < 11; j++) {
            float tj = -2.2f + 0.4f * j;
            bb[j] = (x >= tj && x < tj + 0.4f) ? 1.f : 0.f;
        }
#pragma unroll
        for (int k = 1; k <= 3; k++) {
            float inv = 1.f / (0.4f * k);
#pragma unroll
            for (int j = 0; j < 11 - k; j++) {
                float tj = -2.2f + 0.4f * j;
                float tjk1 = -2.2f + 0.4f * (j + k + 1);
                bb[j] = (x - tj) * inv * bb[j] + (tjk1 - x) * inv * bb[j + 1];
            }
        }
        float s = x / (1.f + __expf(-x));  // silu (MUFU exp; err << bf16 rounding)
        __nv_bfloat16 shi = __float2bfloat16(s);
        __nv_bfloat16 slo = __float2bfloat16(s - __bfloat162float(shi));
        __nv_bfloat16 h[8];
#pragma unroll
        for (int j = 0; j < 8; j++) h[j] = __float2bfloat16(bb[j]);
        uint2* dst = (uint2*)(g_A + (size_t)lin * K12);
        dst[0] = make_uint2(pkb(h[0], h[1]), pkb(h[2], h[3]));
        dst[1] = make_uint2(pkb(h[4], h[5]), pkb(h[6], h[7]));
        dst[2] = make_uint2(pkb(shi, shi), pkb(slo, __float2bfloat16(0.f)));
    } else if (blk < PREP_A_BLOCKS + PREP_BT_BLOCKS) {
        // ---- build_Bt DIRECT (no smem): thread = (one o, 8 consecutive i) ----
        // Warp lanes span 32 consecutive o -> Wk/scale reads are one 128B line per (i,k).
        // Each thread writes its o-row's contiguous 192B run (12 aligned uint4, full sectors).
        int tb = blk - PREP_A_BLOCKS;
        int o0 = (tb & 15) * 32;          // 16 o-tiles
        int i0 = (tb >> 4) * 64;          // 8 i-tiles (64 i each)
        int t  = threadIdx.x;
        int o  = o0 + (t & 31);           // lane -> o (coalesced)
        int ibase = i0 + (t >> 5) * 8;    // warp -> i-block of 8

        uint4 buf[12];
        __nv_bfloat16* bb16 = (__nv_bfloat16*)buf;
#pragma unroll
        for (int ii = 0; ii < 8; ii++) {
            int i = ibase + ii;
            float s = scale[(size_t)i * UNITS + o];
#pragma unroll
            for (int k = 0; k < 8; k++)
                bb16[ii * 12 + k] = __float2bfloat16(s * Wk[((size_t)i * 8 + k) * UNITS + o]);
            __nv_bfloat16 schi = __float2bfloat16(s);
            __nv_bfloat16 sclo = __float2bfloat16(s - __bfloat162float(schi));
            bb16[ii * 12 + 8]  = schi;
            bb16[ii * 12 + 9]  = sclo;
            bb16[ii * 12 + 10] = schi;
            bb16[ii * 12 + 11] = __float2bfloat16(0.f);
        }
        uint4* dst = (uint4*)(g_Bt + (size_t)o * KDIM + (size_t)ibase * K12);
#pragma unroll
        for (int q = 0; q < 12; q++) dst[q] = buf[q];
    } else {
        // ---- init_out: out[b,o] = bias[o] ----
        int idx = ((blk - PREP_A_BLOCKS - PREP_BT_BLOCKS) * 256 + threadIdx.x) * 4;
        *(float4*)(out + idx) = *(const float4*)(bias + (idx & (UNITS - 1)));
    }
}

// ---------------- GEMM (proven engine): CTA 128x128, 8 warps (32x64, 4x2),
// TK=64, PIPE=4, chunk-level register double-buffering with cross-stage prefetch.
// Safety: CP_WAIT(1)+barrier at iter s => stages <= s+2 complete+visible; buffer (s+1)%4
// refilled only after barrier(s+2); issue_stage(s+4) after barrier(s) writes buffer s%4
// whose reads all precede barrier(s).
__global__ __launch_bounds__(256, 1)
void kan_gemm(float* __restrict__ out) {
    extern __shared__ char dyn[];
    const uint32_t base = smem_u32(dyn);   // PIPE stages of [A 16KB | B 16KB]

    const int t   = threadIdx.x;
    const int wid = t >> 5, lane = t & 31;
    const int wm  = wid & 3;               // 4 warp-rows  -> 32 m each
    const int wn  = wid >> 2;              // 2 warp-cols  -> 64 n each
    const int m0  = blockIdx.y * 128;
    const int n0  = blockIdx.x * 128;
    const int kbase = blockIdx.z * KPER;

    const int crow = t >> 3;               // 0..31
    const int cchk = t & 7;                // 16B chunk
    const __nv_bfloat16* gA = g_A  + (size_t)(m0 + crow) * KDIM + kbase + cchk * 8;
    const __nv_bfloat16* gB = g_Bt + (size_t)(n0 + crow) * KDIM + kbase + cchk * 8;

    auto stage_base = [&](int s) { return base + (uint32_t)(s % PIPE) * 32768u; };

    auto issue_stage = [&](int s) {
        uint32_t sb = stage_base(s);
        const __nv_bfloat16* pa = gA + s * TK;
        const __nv_bfloat16* pb = gB + s * TK;
#pragma unroll
        for (int q = 0; q < 4; q++) {
            uint32_t so = swz((uint32_t)(crow + q * 32) * 128u + (uint32_t)cchk * 16u);
            cp_async16(sb + so,          pa + (size_t)(q * 32) * KDIM);
            cp_async16(sb + 16384u + so, pb + (size_t)(q * 32) * KDIM);
        }
    };

    // prologue: fill all PIPE buffers
#pragma unroll
    for (int s = 0; s < PIPE; s++) { issue_stage(s); CP_COMMIT(); }
    CP_WAIT(2);        // stages 0,1 complete ({2,3} outstanding)
    __syncthreads();   // ... and visible to all threads

    const uint32_t a_row = (uint32_t)(wm * 32 + (lane & 15));
    const uint32_t a_kb  = (uint32_t)((lane >> 4) * 16);
    const uint32_t b_row = (uint32_t)(wn * 64 + (lane & 7) + ((lane >> 4) & 1) * 8);
    const uint32_t b_kb  = (uint32_t)(((lane >> 3) & 1) * 16);

    // register double-buffered fragments
    uint32_t af[2][2][4];   // [buf][mi][reg]
    uint32_t bf[2][4][4];   // [buf][g][reg]

    auto load_chunk = [&](int buf, uint32_t sa, int kk) {
        uint32_t sbB = sa + 16384u;
#pragma unroll
        for (int mi = 0; mi < 2; mi++)
            ldsm_x4(af[buf][mi][0], af[buf][mi][1], af[buf][mi][2], af[buf][mi][3],
                    sa + swz((a_row + mi * 16) * 128u + a_kb + (uint32_t)kk * 32u));
#pragma unroll
        for (int g = 0; g < 4; g++)
            ldsm_x4(bf[buf][g][0], bf[buf][g][1], bf[buf][g][2], bf[buf][g][3],
                    sbB + swz((b_row + g * 16) * 128u + b_kb + (uint32_t)kk * 32u));
    };

    float acc[2][8][4];
#pragma unroll
    for (int mi = 0; mi < 2; mi++)
#pragma unroll
        for (int ni = 0; ni < 8; ni++)
#pragma unroll
            for (int r = 0; r < 4; r++) acc[mi][ni][r] = 0.f;

    auto mma_chunk = [&](int buf) {
#pragma unroll
        for (int mi = 0; mi < 2; mi++)
#pragma unroll
            for (int g = 0; g < 4; g++) {
                mma16816(acc[mi][2 * g + 0], af[buf][mi], bf[buf][g][0], bf[buf][g][1]);
                mma16816(acc[mi][2 * g + 1], af[buf][mi], bf[buf][g][2], bf[buf][g][3]);
            }
    };

    int cur = 0;
    load_chunk(0, stage_base(0), 0);   // prime chunk (0,0)

    for (int s = 0; s < STAGES; ++s) {
        uint32_t sa = stage_base(s);
#pragma unroll
        for (int kk = 0; kk < 3; kk++) {
            load_chunk(cur ^ 1, sa, kk + 1);
            mma_chunk(cur);
            cur ^= 1;
        }
        CP_WAIT(1);
        __syncthreads();
        if (s + PIPE < STAGES) issue_stage(s + PIPE);
        CP_COMMIT();
        if (s + 1 < STAGES) load_chunk(cur ^ 1, stage_base(s + 1), 0);
        mma_chunk(cur);
        cur ^= 1;
    }

    // epilogue: atomic-accumulate into bias-initialized out
    const int er = lane >> 2;
    const int ec = (lane & 3) * 2;
#pragma unroll
    for (int mi = 0; mi < 2; mi++) {
#pragma unroll
        for (int ni = 0; ni < 8; ni++) {
            int row = m0 + wm * 32 + mi * 16 + er;
            int col = n0 + wn * 64 + ni * 8 + ec;
            float* p0 = out + (size_t)row * UNITS + col;
            red_add_f32(p0 + 0, acc[mi][ni][0]);
            red_add_f32(p0 + 1, acc[mi][ni][1]);
            float* p1 = p0 + 8 * UNITS;
            red_add_f32(p1 + 0, acc[mi][ni][2]);
            red_add_f32(p1 + 1, acc[mi][ni][3]);
        }
    }
}

// ---------------- launch ----------------
extern "C" void kernel_launch(void* const* d_in, const int* in_sizes, int n_in,
                              void* d_out, int out_size) {
    const float* x    = (const float*)d_in[0];  // (1024, 512)
    const float* wk   = (const float*)d_in[1];  // (512, 8, 512)
    const float* sc   = (const float*)d_in[2];  // (512, 512)
    const float* bias = (const float*)d_in[3];  // (512,)
    float* out = (float*)d_out;                 // (1024, 512)

    prep<<<PREP_A_BLOCKS + PREP_BT_BLOCKS + PREP_OUT_BLOCKS, 256>>>(x, wk, sc, bias, out);

    const int dsmem = PIPE * 32768;  // 128 KB: 4 stages of [A 16KB | B 16KB]
    cudaFuncSetAttribute(kan_gemm, cudaFuncAttributeMaxDynamicSharedMemorySize, dsmem);
    kan_gemm<<<dim3(UNITS / 128, BATCH / 128, KSPLIT), 256, dsmem>>>(out);
}

// round 16
// speedup vs baseline: 1.1523x; 1.1523x over previous
#include <cuda_runtime.h>
#include <cuda_bf16.h>
#include <cstdint>

// ---------------- problem constants ----------------
#define BATCH  1024
#define INSZ   512
#define UNITS  512
#define K12    12
#define KDIM   (INSZ * K12)      // 6144
#define KSPLIT 4
#define KPER   (KDIM / KSPLIT)   // 1536
#define TK     64                // K columns per stage (128 B/row bf16)
#define STAGES (KPER / TK)       // 24
#define PIPE   4                 // cp.async pipeline depth

// fused prep dispatch (256 threads each, NO smem anywhere).
// ORDER MATTERS: Bt blocks FIRST so their latency-bound bodies overlap the A/out blocks.
#define PREP_BT_BLOCKS  ((UNITS / 32) * (INSZ / 16))  // 512: 16 o-tiles x 32 i-tiles
#define PREP_A_BLOCKS   ((BATCH * INSZ) / 256)        // 2048
#define PREP_OUT_BLOCKS ((BATCH * UNITS / 4) / 256)   // 512

// ---------------- scratch ----------------
__device__ __align__(16) __nv_bfloat16 g_A[(size_t)BATCH * KDIM];     // 12.6 MB
__device__ __align__(16) __nv_bfloat16 g_Bt[(size_t)UNITS * KDIM];    // 6.3 MB

// ---------------- helpers ----------------
__device__ __forceinline__ uint32_t smem_u32(const void* p) {
    uint32_t a;
    asm("{ .reg .u64 t; cvta.to.shared.u64 t, %1; cvt.u32.u64 %0, t; }" : "=r"(a) : "l"(p));
    return a;
}
__device__ __forceinline__ uint32_t swz(uint32_t off) { return off ^ ((off >> 3) & 0x70); }

__device__ __forceinline__ void cp_async16(uint32_t saddr, const void* g) {
    asm volatile("cp.async.cg.shared.global [%0], [%1], 16;" :: "r"(saddr), "l"(g) : "memory");
}
#define CP_COMMIT() asm volatile("cp.async.commit_group;" ::: "memory")
#define CP_WAIT(N)  asm volatile("cp.async.wait_group %0;" :: "n"(N) : "memory")

__device__ __forceinline__ void ldsm_x4(uint32_t& r0, uint32_t& r1, uint32_t& r2, uint32_t& r3,
                                        uint32_t addr) {
    asm volatile("ldmatrix.sync.aligned.m8n8.x4.shared.b16 {%0,%1,%2,%3}, [%4];"
                 : "=r"(r0), "=r"(r1), "=r"(r2), "=r"(r3) : "r"(addr));
}
__device__ __forceinline__ void mma16816(float* c, const uint32_t* a, uint32_t b0, uint32_t b1) {
    asm volatile("mma.sync.aligned.m16n8k16.row.col.f32.bf16.bf16.f32 "
                 "{%0,%1,%2,%3}, {%4,%5,%6,%7}, {%8,%9}, {%0,%1,%2,%3};"
                 : "+f"(c[0]), "+f"(c[1]), "+f"(c[2]), "+f"(c[3])
                 : "r"(a[0]), "r"(a[1]), "r"(a[2]), "r"(a[3]), "r"(b0), "r"(b1));
}
__device__ __forceinline__ void red_add_f32(float* p, float v) {
    asm volatile("red.global.add.f32 [%0], %1;" :: "l"(p), "f"(v) : "memory");
}
__device__ __forceinline__ unsigned pkb(__nv_bfloat16 a, __nv_bfloat16 b) {
    return (unsigned)__bfloat16_as_ushort(a) | ((unsigned)__bfloat16_as_ushort(b) << 16);
}

// ---------------- fused prep (NO smem): build_Bt(direct, FIRST) | build_A | init_out ----------------
__global__ void prep(const float* __restrict__ X, const float* __restrict__ Wk,
                     const float* __restrict__ scale, const float* __restrict__ bias,
                     float* __restrict__ out) {
    int blk = blockIdx.x;
    if (blk < PREP_BT_BLOCKS) {
        // ---- build_Bt DIRECT: thread = (one o, 2 consecutive i). Warp lanes span 32
        // consecutive o -> every Wk/scale read is one 128B line. Each thread writes its
        // o-row's contiguous 48B run (3 aligned uint4). Short critical path; 512 blocks
        // placed FIRST so their latency overlaps the A/out ranges.
        int tb = blk;
        int o0 = (tb & 15) * 32;          // 16 o-tiles
        int i0 = (tb >> 4) * 16;          // 32 i-tiles (16 i each)
        int t  = threadIdx.x;
        int o  = o0 + (t & 31);           // lane -> o (coalesced)
        int ibase = i0 + (t >> 5) * 2;    // warp -> i-block of 2

        uint4 buf[3];
        __nv_bfloat16* bb16 = (__nv_bfloat16*)buf;
#pragma unroll
        for (int ii = 0; ii < 2; ii++) {
            int i = ibase + ii;
            float s = scale[(size_t)i * UNITS + o];
#pragma unroll
            for (int k = 0; k < 8; k++)
                bb16[ii * 12 + k] = __float2bfloat16(s * Wk[((size_t)i * 8 + k) * UNITS + o]);
            __nv_bfloat16 schi = __float2bfloat16(s);
            __nv_bfloat16 sclo = __float2bfloat16(s - __bfloat162float(schi));
            bb16[ii * 12 + 8]  = schi;
            bb16[ii * 12 + 9]  = sclo;
            bb16[ii * 12 + 10] = schi;
            bb16[ii * 12 + 11] = __float2bfloat16(0.f);
        }
        uint4* dst = (uint4*)(g_Bt + (size_t)o * KDIM + (size_t)ibase * K12);
        dst[0] = buf[0]; dst[1] = buf[1]; dst[2] = buf[2];
    } else if (blk < PREP_BT_BLOCKS + PREP_A_BLOCKS) {
        // ---- build_A: A[b, i*12 + c] = {8 cubic B-spline bases, shi, shi, slo, 0} ----
        int lin = (blk - PREP_BT_BLOCKS) * 256 + threadIdx.x;
        float x = X[lin];
        float bb[11];
#pragma unroll
        for (int j = 0; j < 11; j++) {
            float tj = -2.2f + 0.4f * j;
            bb[j] = (x >= tj && x < tj + 0.4f) ? 1.f : 0.f;
        }
#pragma unroll
        for (int k = 1; k <= 3; k++) {
            float inv = 1.f / (0.4f * k);
#pragma unroll
            for (int j = 0; j < 11 - k; j++) {
                float tj = -2.2f + 0.4f * j;
                float tjk1 = -2.2f + 0.4f * (j + k + 1);
                bb[j] = (x - tj) * inv * bb[j] + (tjk1 - x) * inv * bb[j + 1];
            }
        }
        float s = x / (1.f + __expf(-x));  // silu (MUFU exp; err << bf16 rounding)
        __nv_bfloat16 shi = __float2bfloat16(s);
        __nv_bfloat16 slo = __float2bfloat16(s - __bfloat162float(shi));
        __nv_bfloat16 h[8];
#pragma unroll
        for (int j = 0; j < 8; j++) h[j] = __float2bfloat16(bb[j]);
        uint2* dst = (uint2*)(g_A + (size_t)lin * K12);
        dst[0] = make_uint2(pkb(h[0], h[1]), pkb(h[2], h[3]));
        dst[1] = make_uint2(pkb(h[4], h[5]), pkb(h[6], h[7]));
        dst[2] = make_uint2(pkb(shi, shi), pkb(slo, __float2bfloat16(0.f)));
    } else {
        // ---- init_out: out[b,o] = bias[o] ----
        int idx = ((blk - PREP_BT_BLOCKS - PREP_A_BLOCKS) * 256 + threadIdx.x) * 4;
        *(float4*)(out + idx) = *(const float4*)(bias + (idx & (UNITS - 1)));
    }
}

// ---------------- GEMM (proven engine): CTA 128x128, 8 warps (32x64, 4x2),
// TK=64, PIPE=4, chunk-level register double-buffering with cross-stage prefetch.
// Safety: CP_WAIT(1)+barrier at iter s => stages <= s+2 complete+visible; buffer (s+1)%4
// refilled only after barrier(s+2); issue_stage(s+4) after barrier(s) writes buffer s%4
// whose reads all precede barrier(s).
__global__ __launch_bounds__(256, 1)
void kan_gemm(float* __restrict__ out) {
    extern __shared__ char dyn[];
    const uint32_t base = smem_u32(dyn);   // PIPE stages of [A 16KB | B 16KB]

    const int t   = threadIdx.x;
    const int wid = t >> 5, lane = t & 31;
    const int wm  = wid & 3;               // 4 warp-rows  -> 32 m each
    const int wn  = wid >> 2;              // 2 warp-cols  -> 64 n each
    const int m0  = blockIdx.y * 128;
    const int n0  = blockIdx.x * 128;
    const int kbase = blockIdx.z * KPER;

    const int crow = t >> 3;               // 0..31
    const int cchk = t & 7;                // 16B chunk
    const __nv_bfloat16* gA = g_A  + (size_t)(m0 + crow) * KDIM + kbase + cchk * 8;
    const __nv_bfloat16* gB = g_Bt + (size_t)(n0 + crow) * KDIM + kbase + cchk * 8;

    auto stage_base = [&](int s) { return base + (uint32_t)(s % PIPE) * 32768u; };

    auto issue_stage = [&](int s) {
        uint32_t sb = stage_base(s);
        const __nv_bfloat16* pa = gA + s * TK;
        const __nv_bfloat16* pb = gB + s * TK;
#pragma unroll
        for (int q = 0; q < 4; q++) {
            uint32_t so = swz((uint32_t)(crow + q * 32) * 128u + (uint32_t)cchk * 16u);
            cp_async16(sb + so,          pa + (size_t)(q * 32) * KDIM);
            cp_async16(sb + 16384u + so, pb + (size_t)(q * 32) * KDIM);
        }
    };

    // prologue: fill all PIPE buffers
#pragma unroll
    for (int s = 0; s < PIPE; s++) { issue_stage(s); CP_COMMIT(); }
    CP_WAIT(2);        // stages 0,1 complete ({2,3} outstanding)
    __syncthreads();   // ... and visible to all threads

    const uint32_t a_row = (uint32_t)(wm * 32 + (lane & 15));
    const uint32_t a_kb  = (uint32_t)((lane >> 4) * 16);
    const uint32_t b_row = (uint32_t)(wn * 64 + (lane & 7) + ((lane >> 4) & 1) * 8);
    const uint32_t b_kb  = (uint32_t)(((lane >> 3) & 1) * 16);

    // register double-buffered fragments
    uint32_t af[2][2][4];   // [buf][mi][reg]
    uint32_t bf[2][4][4];   // [buf][g][reg]

    auto load_chunk = [&](int buf, uint32_t sa, int kk) {
        uint32_t sbB = sa + 16384u;
#pragma unroll
        for (int mi = 0; mi < 2; mi++)
            ldsm_x4(af[buf][mi][0], af[buf][mi][1], af[buf][mi][2], af[buf][mi][3],
                    sa + swz((a_row + mi * 16) * 128u + a_kb + (uint32_t)kk * 32u));
#pragma unroll
        for (int g = 0; g < 4; g++)
            ldsm_x4(bf[buf][g][0], bf[buf][g][1], bf[buf][g][2], bf[buf][g][3],
                    sbB + swz((b_row + g * 16) * 128u + b_kb + (uint32_t)kk * 32u));
    };

    float acc[2][8][4];
#pragma unroll
    for (int mi = 0; mi < 2; mi++)
#pragma unroll
        for (int ni = 0; ni < 8; ni++)
#pragma unroll
            for (int r = 0; r < 4; r++) acc[mi][ni][r] = 0.f;

    auto mma_chunk = [&](int buf) {
#pragma unroll
        for (int mi = 0; mi < 2; mi++)
#pragma unroll
            for (int g = 0; g < 4; g++) {
                mma16816(acc[mi][2 * g + 0], af[buf][mi], bf[buf][g][0], bf[buf][g][1]);
                mma16816(acc[mi][2 * g + 1], af[buf][mi], bf[buf][g][2], bf[buf][g][3]);
            }
    };

    int cur = 0;
    load_chunk(0, stage_base(0), 0);   // prime chunk (0,0)

    for (int s = 0; s < STAGES; ++s) {
        uint32_t sa = stage_base(s);
#pragma unroll
        for (int kk = 0; kk < 3; kk++) {
            load_chunk(cur ^ 1, sa, kk + 1);
            mma_chunk(cur);
            cur ^= 1;
        }
        CP_WAIT(1);
        __syncthreads();
        if (s + PIPE < STAGES) issue_stage(s + PIPE);
        CP_COMMIT();
        if (s + 1 < STAGES) load_chunk(cur ^ 1, stage_base(s + 1), 0);
        mma_chunk(cur);
        cur ^= 1;
    }

    // epilogue: atomic-accumulate into bias-initialized out
    const int er = lane >> 2;
    const int ec = (lane & 3) * 2;
#pragma unroll
    for (int mi = 0; mi < 2; mi++) {
#pragma unroll
        for (int ni = 0; ni < 8; ni++) {
            int row = m0 + wm * 32 + mi * 16 + er;
            int col = n0 + wn * 64 + ni * 8 + ec;
            float* p0 = out + (size_t)row * UNITS + col;
            red_add_f32(p0 + 0, acc[mi][ni][0]);
            red_add_f32(p0 + 1, acc[mi][ni][1]);
            float* p1 = p0 + 8 * UNITS;
            red_add_f32(p1 + 0, acc[mi][ni][2]);
            red_add_f32(p1 + 1, acc[mi][ni][3]);
        }
    }
}

// ---------------- launch ----------------
extern "C" void kernel_launch(void* const* d_in, const int* in_sizes, int n_in,
                              void* d_out, int out_size) {
    const float* x    = (const float*)d_in[0];  // (1024, 512)
    const float* wk   = (const float*)d_in[1];  // (512, 8, 512)
    const float* sc   = (const float*)d_in[2];  // (512, 512)
    const float* bias = (const float*)d_in[3];  // (512,)
    float* out = (float*)d_out;                 // (1024, 512)

    prep<<<PREP_BT_BLOCKS + PREP_A_BLOCKS + PREP_OUT_BLOCKS, 256>>>(x, wk, sc, bias, out);

    const int dsmem = PIPE * 32768;  // 128 KB: 4 stages of [A 16KB | B 16KB]
    cudaFuncSetAttribute(kan_gemm, cudaFuncAttributeMaxDynamicSharedMemorySize, dsmem);
    kan_gemm<<<dim3(UNITS / 128, BATCH / 128, KSPLIT), 256, dsmem>>>(out);
}